// round 12
// baseline (speedup 1.0000x reference)
#include <cuda_runtime.h>
#include <cuda_fp16.h>
#include <math.h>
#include <stdint.h>

// Problem constants
#define Bq 2
#define Sq 2048
#define Dm 1024
#define Ff 4096
#define Hh 16
#define Dhd 64
#define Mrows 4096  // B*S

// ---------------------------------------------------------------------------
// Scratch (device globals)
// ---------------------------------------------------------------------------
__device__ float g_tmp[(size_t)Mrows * Dm];
__device__ float g_h[(size_t)Mrows * Dm];
__device__ float g_cos[Sq * 32];
__device__ float g_sin[Sq * 32];

__device__ __half g_xf[(size_t)Mrows * Dm];
__device__ __half g_wb[12582912];
#define OFF_INW 0
#define OFF_OUTW 3145728
#define OFF_W1 4194304
#define OFF_W2 8388608
__device__ __half g_qq[(size_t)Bq * Hh * Sq * 64];
__device__ __half g_kk[(size_t)Bq * Hh * Sq * 64];
__device__ __half g_vv[(size_t)Bq * Hh * Sq * 64];
__device__ __half g_at[(size_t)Mrows * Dm];
__device__ __half g_hf[(size_t)Mrows * Dm];
__device__ __half g_ff[(size_t)Mrows * Ff];

__device__ __forceinline__ uint32_t smem_u32(const void* p) {
    uint32_t a;
    asm("{ .reg .u64 t; cvta.to.shared.u64 t, %1; cvt.u32.u64 %0, t; }"
        : "=r"(a) : "l"(p));
    return a;
}
__device__ __forceinline__ void cp16(uint32_t dst, const void* src) {
    asm volatile("cp.async.cg.shared.global [%0], [%1], 16;"
                 :: "r"(dst), "l"(src));
}
#define CP_COMMIT() asm volatile("cp.async.commit_group;" ::: "memory")
#define CP_WAIT1()  asm volatile("cp.async.wait_group 1;" ::: "memory")
#define CP_WAIT0()  asm volatile("cp.async.wait_group 0;" ::: "memory")

__device__ __forceinline__ void ldsm_x4(uint32_t* r, uint32_t addr)
{
    asm volatile("ldmatrix.sync.aligned.m8n8.x4.shared.b16 {%0,%1,%2,%3}, [%4];"
                 : "=r"(r[0]), "=r"(r[1]), "=r"(r[2]), "=r"(r[3]) : "r"(addr));
}
__device__ __forceinline__ void ldsm_x4_t(uint32_t* r, uint32_t addr)
{
    asm volatile("ldmatrix.sync.aligned.m8n8.x4.trans.shared.b16 {%0,%1,%2,%3}, [%4];"
                 : "=r"(r[0]), "=r"(r[1]), "=r"(r[2]), "=r"(r[3]) : "r"(addr));
}
__device__ __forceinline__ void mma_f16(float* c, const uint32_t* a,
                                        uint32_t b0, uint32_t b1)
{
    asm volatile(
        "mma.sync.aligned.m16n8k16.row.col.f32.f16.f16.f32 "
        "{%0,%1,%2,%3}, {%4,%5,%6,%7}, {%8,%9}, {%0,%1,%2,%3};"
        : "+f"(c[0]), "+f"(c[1]), "+f"(c[2]), "+f"(c[3])
        : "r"(a[0]), "r"(a[1]), "r"(a[2]), "r"(a[3]), "r"(b0), "r"(b1));
}
__device__ __forceinline__ uint32_t pack_f16x2(float lo, float hi)
{
    uint32_t r;
    asm("cvt.rn.f16x2.f32 %0, %1, %2;" : "=r"(r) : "f"(hi), "f"(lo));
    return r;
}

// ===========================================================================
// RoPE table kernel
// ===========================================================================
__global__ __launch_bounds__(256) void rope_table_kernel()
{
    int idx = blockIdx.x * 256 + threadIdx.x;
    if (idx >= Sq * 32) return;
    int s = idx >> 5;
    int i = idx & 31;
    double invd = exp(-(double)i * (9.210340371976184 / 32.0));
    float invf = (float)invd;
    float angf = (float)s * invf;
    double a = (double)angf;
    g_cos[idx] = (float)cos(a);
    g_sin[idx] = (float)sin(a);
}

// ===========================================================================
// Fused fp32 -> fp16 converter, 16 elems (4 float4) per thread for MLP=4.
// Segment boundaries (in float4 units) are all divisible by 4.
// ===========================================================================
#define SEG_X   1048576
#define SEG_INW (SEG_X + 786432)
#define SEG_OUW (SEG_INW + 262144)
#define SEG_W1  (SEG_OUW + 1048576)
#define SEG_W2  (SEG_W1 + 1048576)

__global__ __launch_bounds__(256) void cvt_all(
    const float* __restrict__ x, const float* __restrict__ in_w,
    const float* __restrict__ out_w, const float* __restrict__ w1,
    const float* __restrict__ w2)
{
    int g = blockIdx.x * 256 + threadIdx.x;
    if (g >= SEG_W2 / 4) return;
    int idx0 = g * 4;
    const float* src;
    __half* dst;
    int base;
    if (idx0 < SEG_X)        { src = x;     dst = g_xf;            base = 0; }
    else if (idx0 < SEG_INW) { src = in_w;  dst = g_wb + OFF_INW;  base = SEG_X; }
    else if (idx0 < SEG_OUW) { src = out_w; dst = g_wb + OFF_OUTW; base = SEG_INW; }
    else if (idx0 < SEG_W1)  { src = w1;    dst = g_wb + OFF_W1;   base = SEG_OUW; }
    else                     { src = w2;    dst = g_wb + OFF_W2;   base = SEG_W1; }
    size_t off = (size_t)(idx0 - base) * 4;
    float4 v0 = *(const float4*)(src + off);
    float4 v1 = *(const float4*)(src + off + 4);
    float4 v2 = *(const float4*)(src + off + 8);
    float4 v3 = *(const float4*)(src + off + 12);
    uint4 o;
    o.x = pack_f16x2(v0.x, v0.y); o.y = pack_f16x2(v0.z, v0.w);
    o.z = pack_f16x2(v1.x, v1.y); o.w = pack_f16x2(v1.z, v1.w);
    *(uint4*)(dst + off) = o;
    o.x = pack_f16x2(v2.x, v2.y); o.y = pack_f16x2(v2.z, v2.w);
    o.z = pack_f16x2(v3.x, v3.y); o.w = pack_f16x2(v3.z, v3.w);
    *(uint4*)(dst + off + 8) = o;
}

// ===========================================================================
// fp16 GEMM, CTA 256x128, warp tile 64x64 (4m x 2n warps), BK=32.
// 3-stage cp.async pipeline. pitch 80B.
// smem/stage: A 256x80=20480 + W 128x80=10240 = 30720; x3 = 92160 bytes.
// mode 0: fp32 out. mode 1: relu + fp16 out. mode 2: QKV + RoPE epilogue.
// ===========================================================================
#define GPITCH 80
#define GARRA 20480
#define GSTG 30720

__global__ __launch_bounds__(256, 1) void gemm_f16(
    const __half* __restrict__ A, const __half* __restrict__ W,
    const float* __restrict__ bias, float* __restrict__ Cf,
    __half* __restrict__ Ch, __half* __restrict__ Qd,
    __half* __restrict__ Kd, __half* __restrict__ Vd,
    int N, int K, int mode)
{
    extern __shared__ char dsm[];
    uint32_t sb = smem_u32(dsm);

    int tid = threadIdx.x;
    int lane = tid & 31, warp = tid >> 5;
    int wm = warp & 3;        // 4 warps along M (64 rows each)
    int wn = warp >> 2;       // 2 warps along N (64 cols each)
    int row0 = blockIdx.y * 256;
    int col0 = blockIdx.x * 128;

    float acc[4][8][4];
#pragma unroll
    for (int i = 0; i < 4; i++)
#pragma unroll
        for (int j = 0; j < 8; j++)
#pragma unroll
            for (int f = 0; f < 4; f++) acc[i][j][f] = 0.f;

    int frow = lane & 15;
    int fko  = (lane >> 4) << 3;

    // staging map: A 1024 chunks + W 512 chunks = 1536, 6 per thread
    const __half* gsrc[6];
    uint32_t soff[6];
#pragma unroll
    for (int i = 0; i < 6; i++) {
        int f = tid + i * 256;
        if (f < 1024) {
            int r = f >> 2, q = f & 3;
            gsrc[i] = A + (size_t)(row0 + r) * K + q * 8;
            soff[i] = r * GPITCH + q * 16;
        } else {
            int fw = f - 1024;
            int r = fw >> 2, q = fw & 3;
            gsrc[i] = W + (size_t)(col0 + r) * K + q * 8;
            soff[i] = GARRA + r * GPITCH + q * 16;
        }
    }

    int nk = K >> 5;

    // prologue: tiles 0, 1
#pragma unroll
    for (int p = 0; p < 2; p++) {
        uint32_t stg = sb + p * GSTG;
#pragma unroll
        for (int i = 0; i < 6; i++)
            cp16(stg + soff[i], gsrc[i] + p * 32);
        CP_COMMIT();
    }

    int buf = 0;
    for (int t = 0; t < nk; t++) {
        if (t + 1 < nk) CP_WAIT1(); else CP_WAIT0();
        __syncthreads();
        if (t + 2 < nk) {
            int pbuf = buf + 2; if (pbuf >= 3) pbuf -= 3;
            uint32_t stg = sb + pbuf * GSTG;
            int kt = (t + 2) * 32;
#pragma unroll
            for (int i = 0; i < 6; i++)
                cp16(stg + soff[i], gsrc[i] + kt);
            CP_COMMIT();
        }

        uint32_t aA = sb + buf * GSTG;
        uint32_t aW = aA + GARRA;

#pragma unroll
        for (int s = 0; s < 2; s++) {
            int ko = s * 16 + fko;
            uint32_t af[4][4];
#pragma unroll
            for (int mt = 0; mt < 4; mt++) {
                int off = (wm * 64 + mt * 16 + frow) * GPITCH + ko * 2;
                ldsm_x4(af[mt], aA + off);
            }
#pragma unroll
            for (int bt = 0; bt < 4; bt++) {
                uint32_t bf[4];
                int off = (wn * 64 + bt * 16 + frow) * GPITCH + ko * 2;
                ldsm_x4(bf, aW + off);
#pragma unroll
                for (int mt = 0; mt < 4; mt++)
#pragma unroll
                    for (int h = 0; h < 2; h++)
                        mma_f16(acc[mt][bt * 2 + h], af[mt], bf[h], bf[h + 2]);
            }
        }
        if (++buf == 3) buf = 0;
    }

    int tr = lane >> 2, tc = (lane & 3) * 2;
#pragma unroll
    for (int mt = 0; mt < 4; mt++) {
#pragma unroll
        for (int nt = 0; nt < 8; nt++) {
            int col = col0 + wn * 64 + nt * 8 + tc;
            float2 bv = *(const float2*)(bias + col);
            int r0 = row0 + wm * 64 + mt * 16 + tr;
            float o[4];
            o[0] = acc[mt][nt][0] + bv.x;
            o[1] = acc[mt][nt][1] + bv.y;
            o[2] = acc[mt][nt][2] + bv.x;
            o[3] = acc[mt][nt][3] + bv.y;
            if (mode == 0) {
                *(float2*)(Cf + (size_t)r0 * N + col) = make_float2(o[0], o[1]);
                *(float2*)(Cf + (size_t)(r0 + 8) * N + col) = make_float2(o[2], o[3]);
            } else if (mode == 1) {
#pragma unroll
                for (int i = 0; i < 4; i++) o[i] = fmaxf(o[i], 0.f);
                *(uint32_t*)(Ch + (size_t)r0 * N + col) = pack_f16x2(o[0], o[1]);
                *(uint32_t*)(Ch + (size_t)(r0 + 8) * N + col) = pack_f16x2(o[2], o[3]);
            } else {
                int sector = col >> 10;
                int cc = col & 1023;
                int h = cc >> 6;
                int e = cc & 63;
                int i = e >> 1;
#pragma unroll
                for (int rg = 0; rg < 2; rg++) {
                    int r = r0 + rg * 8;
                    int s = r & (Sq - 1);
                    int b = r >> 11;
                    float v0 = o[rg * 2], v1 = o[rg * 2 + 1];
                    if (sector < 2) {
                        float c = g_cos[s * 32 + i];
                        float sn = g_sin[s * 32 + i];
                        float re = v0 * c - v1 * sn;
                        float ro = v0 * sn + v1 * c;
                        v0 = re; v1 = ro;
                    }
                    __half* dst = (sector == 0) ? Qd : (sector == 1) ? Kd : Vd;
                    size_t d = ((size_t)(b * Hh + h) * Sq + s) * 64 + e;
                    *(uint32_t*)(dst + d) = pack_f16x2(v0, v1);
                }
            }
        }
    }
}

// ===========================================================================
// Flash attention, pure fp16, 3-stage cp.async K/V pipeline (unchanged).
// ===========================================================================
#define APITCH 144
#define AQ0 0
#define AKV0 18432
#define AARR 9216
#define KVSTG 18432
#define ATT_SMEM 73728

__global__ __launch_bounds__(256) void attn_mma(
    const __half* __restrict__ Qq, const __half* __restrict__ Kk,
    const __half* __restrict__ Vv, __half* __restrict__ at)
{
    extern __shared__ char dsm[];
    uint32_t sb = smem_u32(dsm);

    int tid = threadIdx.x;
    int lane = tid & 31, warp = tid >> 5;
    int bh = blockIdx.y;
    int b = bh >> 4, hh = bh & 15;
    int q0 = blockIdx.x * 128;

    size_t hbase = (size_t)bh * Sq * 64;

    const __half* kvsrc[4];
    uint32_t kvoff[4];
#pragma unroll
    for (int i = 0; i < 4; i++) {
        int f = tid + i * 256;
        int a = f >> 9, rem = f & 511, r = rem >> 3, q = rem & 7;
        kvsrc[i] = (a ? Vv : Kk) + hbase + (size_t)r * 64 + q * 8;
        kvoff[i] = a * AARR + r * APITCH + q * 16;
    }

#pragma unroll
    for (int i = 0; i < 4; i++) {
        int f = tid + i * 256;
        int r = f >> 3, q = f & 7;
        cp16(sb + AQ0 + r * APITCH + q * 16,
             Qq + hbase + (size_t)(q0 + r) * 64 + q * 8);
    }
#pragma unroll
    for (int i = 0; i < 4; i++)
        cp16(sb + AKV0 + kvoff[i], kvsrc[i]);
    CP_COMMIT();
#pragma unroll
    for (int i = 0; i < 4; i++)
        cp16(sb + AKV0 + KVSTG + kvoff[i], kvsrc[i] + (size_t)64 * 64);
    CP_COMMIT();

    int frow = lane & 15;
    int fko  = (lane >> 4) << 3;

    uint32_t aQ[4][4];
    float m0 = -1e30f, m1 = -1e30f, l0 = 0.f, l1 = 0.f;
    float oacc[8][4];
#pragma unroll
    for (int j = 0; j < 8; j++)
#pragma unroll
        for (int f = 0; f < 4; f++) oacc[j][f] = 0.f;

    const int NT = Sq / 64;
    int buf = 0;
    for (int t = 0; t < NT; t++) {
        if (t + 1 < NT) CP_WAIT1(); else CP_WAIT0();
        __syncthreads();
        if (t + 2 < NT) {
            int pbuf = buf + 2; if (pbuf >= 3) pbuf -= 3;
            uint32_t stg = sb + AKV0 + pbuf * KVSTG;
            size_t kofs = (size_t)(t + 2) * 64 * 64;
#pragma unroll
            for (int i = 0; i < 4; i++)
                cp16(stg + kvoff[i], kvsrc[i] + kofs);
            CP_COMMIT();
        }

        if (t == 0) {
#pragma unroll
            for (int c = 0; c < 4; c++) {
                int off = (warp * 16 + frow) * APITCH + (c * 16 + fko) * 2;
                ldsm_x4(aQ[c], sb + AQ0 + off);
            }
        }

        uint32_t aKB = sb + AKV0 + buf * KVSTG;
        uint32_t aVB = aKB + AARR;

        float sacc[8][4];
#pragma unroll
        for (int j = 0; j < 8; j++)
#pragma unroll
            for (int f = 0; f < 4; f++) sacc[j][f] = 0.f;

#pragma unroll
        for (int kd = 0; kd < 4; kd++) {
#pragma unroll
            for (int bt = 0; bt < 4; bt++) {
                uint32_t kf[4];
                int off = (bt * 16 + frow) * APITCH + (kd * 16 + fko) * 2;
                ldsm_x4(kf, aKB + off);
#pragma unroll
                for (int h = 0; h < 2; h++) {
                    int nt = bt * 2 + h;
                    mma_f16(sacc[nt], aQ[kd], kf[h], kf[h + 2]);
                }
            }
        }

        float rmax0 = -1e30f, rmax1 = -1e30f;
#pragma unroll
        for (int j = 0; j < 8; j++) {
            rmax0 = fmaxf(rmax0, fmaxf(sacc[j][0], sacc[j][1]));
            rmax1 = fmaxf(rmax1, fmaxf(sacc[j][2], sacc[j][3]));
        }
        rmax0 = fmaxf(rmax0, __shfl_xor_sync(0xffffffffu, rmax0, 1));
        rmax0 = fmaxf(rmax0, __shfl_xor_sync(0xffffffffu, rmax0, 2));
        rmax1 = fmaxf(rmax1, __shfl_xor_sync(0xffffffffu, rmax1, 1));
        rmax1 = fmaxf(rmax1, __shfl_xor_sync(0xffffffffu, rmax1, 2));

        float mn0 = fmaxf(m0, 0.125f * rmax0);
        float mn1 = fmaxf(m1, 0.125f * rmax1);
        float corr0 = __expf(m0 - mn0);
        float corr1 = __expf(m1 - mn1);
        m0 = mn0; m1 = mn1;

        uint32_t pah[4][4];
        float ps0 = 0.f, ps1 = 0.f;
#pragma unroll
        for (int c = 0; c < 4; c++) {
#pragma unroll
            for (int u = 0; u < 2; u++) {
                int j = 2 * c + u;
                float p0 = __expf(0.125f * sacc[j][0] - mn0);
                float p1 = __expf(0.125f * sacc[j][1] - mn0);
                float p2 = __expf(0.125f * sacc[j][2] - mn1);
                float p3 = __expf(0.125f * sacc[j][3] - mn1);
                ps0 += p0 + p1;
                ps1 += p2 + p3;
                pah[c][2 * u + 0] = pack_f16x2(p0, p1);
                pah[c][2 * u + 1] = pack_f16x2(p2, p3);
            }
        }
        ps0 += __shfl_xor_sync(0xffffffffu, ps0, 1);
        ps0 += __shfl_xor_sync(0xffffffffu, ps0, 2);
        ps1 += __shfl_xor_sync(0xffffffffu, ps1, 1);
        ps1 += __shfl_xor_sync(0xffffffffu, ps1, 2);
        l0 = l0 * corr0 + ps0;
        l1 = l1 * corr1 + ps1;

#pragma unroll
        for (int j = 0; j < 8; j++) {
            oacc[j][0] *= corr0; oacc[j][1] *= corr0;
            oacc[j][2] *= corr1; oacc[j][3] *= corr1;
        }

#pragma unroll
        for (int c = 0; c < 4; c++) {
#pragma unroll
            for (int g = 0; g < 4; g++) {
                uint32_t vf[4];
                int off = (c * 16 + frow) * APITCH + (g * 16 + fko) * 2;
                ldsm_x4_t(vf, aVB + off);
#pragma unroll
                for (int h2 = 0; h2 < 2; h2++) {
                    int j = g * 2 + h2;
                    mma_f16(oacc[j], pah[c], vf[2 * h2], vf[2 * h2 + 1]);
                }
            }
        }
        if (++buf == 3) buf = 0;
    }

    float inv0 = 1.f / l0, inv1 = 1.f / l1;
    int tr = lane >> 2, tc = (lane & 3) * 2;
    int row0 = b * Sq + q0 + warp * 16 + tr;
#pragma unroll
    for (int j = 0; j < 8; j++) {
        int col = hh * 64 + j * 8 + tc;
        *(uint32_t*)(at + (size_t)row0 * Dm + col) =
            pack_f16x2(oacc[j][0] * inv0, oacc[j][1] * inv0);
        *(uint32_t*)(at + (size_t)(row0 + 8) * Dm + col) =
            pack_f16x2(oacc[j][2] * inv1, oacc[j][3] * inv1);
    }
}

// ===========================================================================
// Fused residual add + LayerNorm (+ optional fp16 output)
// ===========================================================================
__device__ __forceinline__ float block_allreduce(float v, float* sred)
{
#pragma unroll
    for (int o = 16; o; o >>= 1) v += __shfl_xor_sync(0xffffffffu, v, o);
    int w = threadIdx.x >> 5;
    if ((threadIdx.x & 31) == 0) sred[w] = v;
    __syncthreads();
    float t = (threadIdx.x < 8) ? sred[threadIdx.x] : 0.f;
    if (threadIdx.x < 32) {
#pragma unroll
        for (int o = 4; o; o >>= 1) t += __shfl_xor_sync(0xffffffffu, t, o);
        if (threadIdx.x == 0) sred[0] = t;
    }
    __syncthreads();
    float r = sred[0];
    __syncthreads();
    return r;
}

__global__ __launch_bounds__(256) void add_ln_kernel(
    const float* __restrict__ x, const float* __restrict__ y,
    const float* __restrict__ g, const float* __restrict__ bta,
    float* __restrict__ out, __half* __restrict__ oh)
{
    __shared__ float sred[8];
    int row = blockIdx.x;
    int tid = threadIdx.x;
    const float* xr = x + (size_t)row * Dm;
    const float* yr = y + (size_t)row * Dm;

    float4 xv = *(const float4*)(xr + tid * 4);
    float4 yv = *(const float4*)(yr + tid * 4);
    float v[4] = {xv.x + yv.x, xv.y + yv.y, xv.z + yv.z, xv.w + yv.w};

    float sum = v[0] + v[1] + v[2] + v[3];
    sum = block_allreduce(sum, sred);
    float mean = sum * (1.f / (float)Dm);

    float sq = 0.f;
#pragma unroll
    for (int i = 0; i < 4; i++) {
        float d = v[i] - mean;
        sq += d * d;
    }
    sq = block_allreduce(sq, sred);
    float inv = rsqrtf(sq * (1.f / (float)Dm) + 1e-5f);

    float4 gv = *(const float4*)(g + tid * 4);
    float4 bv = *(const float4*)(bta + tid * 4);
    float o[4];
    o[0] = (v[0] - mean) * inv * gv.x + bv.x;
    o[1] = (v[1] - mean) * inv * gv.y + bv.y;
    o[2] = (v[2] - mean) * inv * gv.z + bv.z;
    o[3] = (v[3] - mean) * inv * gv.w + bv.w;
    *(float4*)(out + (size_t)row * Dm + tid * 4) =
        make_float4(o[0], o[1], o[2], o[3]);

    if (oh) {
        uint2 hv;
        hv.x = pack_f16x2(o[0], o[1]);
        hv.y = pack_f16x2(o[2], o[3]);
        *(uint2*)(oh + (size_t)row * Dm + tid * 4) = hv;
    }
}

// ===========================================================================
extern "C" void kernel_launch(void* const* d_in, const int* in_sizes, int n_in,
                              void* d_out, int out_size)
{
    const float* x     = (const float*)d_in[0];
    const float* in_w  = (const float*)d_in[1];
    const float* in_b  = (const float*)d_in[2];
    const float* out_w = (const float*)d_in[3];
    const float* out_b = (const float*)d_in[4];
    const float* w1    = (const float*)d_in[5];
    const float* b1    = (const float*)d_in[6];
    const float* w2    = (const float*)d_in[7];
    const float* b2    = (const float*)d_in[8];
    const float* ln1g  = (const float*)d_in[9];
    const float* ln1b  = (const float*)d_in[10];
    const float* ln2g  = (const float*)d_in[11];
    const float* ln2b  = (const float*)d_in[12];
    float* out = (float*)d_out;

    float *tmp, *hbuf;
    __half *xf, *wb, *qq, *kk, *vv, *at, *hf, *ff;
    cudaGetSymbolAddress((void**)&tmp, g_tmp);
    cudaGetSymbolAddress((void**)&hbuf, g_h);
    cudaGetSymbolAddress((void**)&xf, g_xf);
    cudaGetSymbolAddress((void**)&wb, g_wb);
    cudaGetSymbolAddress((void**)&qq, g_qq);
    cudaGetSymbolAddress((void**)&kk, g_kk);
    cudaGetSymbolAddress((void**)&vv, g_vv);
    cudaGetSymbolAddress((void**)&at, g_at);
    cudaGetSymbolAddress((void**)&hf, g_hf);
    cudaGetSymbolAddress((void**)&ff, g_ff);

    cudaFuncSetAttribute(gemm_f16, cudaFuncAttributeMaxDynamicSharedMemorySize,
                         3 * GSTG);
    cudaFuncSetAttribute(attn_mma, cudaFuncAttributeMaxDynamicSharedMemorySize,
                         ATT_SMEM);

    dim3 tb(256);

    rope_table_kernel<<<(Sq * 32 + 255) / 256, tb>>>();
    cvt_all<<<(SEG_W2 / 4 + 255) / 256, tb>>>(x, in_w, out_w, w1, w2);

    // QKV projection + fused RoPE -> head-major fp16 Q/K/V
    gemm_f16<<<dim3(3072 / 128, Mrows / 256), tb, 3 * GSTG>>>(
        xf, wb + OFF_INW, in_b, nullptr, nullptr, qq, kk, vv, 3 * Dm, Dm, 2);
    // Attention -> fp16
    attn_mma<<<dim3(Sq / 128, Bq * Hh), tb, ATT_SMEM>>>(qq, kk, vv, at);
    // Output projection -> fp32
    gemm_f16<<<dim3(Dm / 128, Mrows / 256), tb, 3 * GSTG>>>(
        at, wb + OFF_OUTW, out_b, tmp, nullptr, nullptr, nullptr, nullptr,
        Dm, Dm, 0);
    // LN1 -> fp32 h + fp16
    add_ln_kernel<<<Mrows, tb>>>(x, tmp, ln1g, ln1b, hbuf, hf);
    // FF1 + ReLU -> fp16
    gemm_f16<<<dim3(Ff / 128, Mrows / 256), tb, 3 * GSTG>>>(
        hf, wb + OFF_W1, b1, nullptr, ff, nullptr, nullptr, nullptr,
        Ff, Dm, 1);
    // FF2 -> fp32
    gemm_f16<<<dim3(Dm / 128, Mrows / 256), tb, 3 * GSTG>>>(
        ff, wb + OFF_W2, b2, tmp, nullptr, nullptr, nullptr, nullptr,
        Dm, Ff, 0);
    // LN2 -> out
    add_ln_kernel<<<Mrows, tb>>>(hbuf, tmp, ln2g, ln2b, out, nullptr);
}

// round 13
// speedup vs baseline: 1.0940x; 1.0940x over previous
#include <cuda_runtime.h>
#include <cuda_fp16.h>
#include <math.h>
#include <stdint.h>

// Problem constants
#define Bq 2
#define Sq 2048
#define Dm 1024
#define Ff 4096
#define Hh 16
#define Dhd 64
#define Mrows 4096  // B*S

// ---------------------------------------------------------------------------
// Scratch (device globals)
// ---------------------------------------------------------------------------
__device__ float g_tmp[(size_t)Mrows * Dm];
__device__ float g_h[(size_t)Mrows * Dm];
__device__ float g_cos[Sq * 32];
__device__ float g_sin[Sq * 32];

__device__ __half g_xf[(size_t)Mrows * Dm];
__device__ __half g_wb[12582912];
#define OFF_INW 0
#define OFF_OUTW 3145728
#define OFF_W1 4194304
#define OFF_W2 8388608
__device__ __half g_qq[(size_t)Bq * Hh * Sq * 64];
__device__ __half g_kk[(size_t)Bq * Hh * Sq * 64];
__device__ __half g_vv[(size_t)Bq * Hh * Sq * 64];
__device__ __half g_at[(size_t)Mrows * Dm];
__device__ __half g_hf[(size_t)Mrows * Dm];
__device__ __half g_ff[(size_t)Mrows * Ff];

__device__ __forceinline__ uint32_t smem_u32(const void* p) {
    uint32_t a;
    asm("{ .reg .u64 t; cvta.to.shared.u64 t, %1; cvt.u32.u64 %0, t; }"
        : "=r"(a) : "l"(p));
    return a;
}
__device__ __forceinline__ void cp16(uint32_t dst, const void* src) {
    asm volatile("cp.async.cg.shared.global [%0], [%1], 16;"
                 :: "r"(dst), "l"(src));
}
#define CP_COMMIT() asm volatile("cp.async.commit_group;" ::: "memory")
#define CP_WAIT1()  asm volatile("cp.async.wait_group 1;" ::: "memory")
#define CP_WAIT0()  asm volatile("cp.async.wait_group 0;" ::: "memory")

__device__ __forceinline__ void ldsm_x4(uint32_t* r, uint32_t addr)
{
    asm volatile("ldmatrix.sync.aligned.m8n8.x4.shared.b16 {%0,%1,%2,%3}, [%4];"
                 : "=r"(r[0]), "=r"(r[1]), "=r"(r[2]), "=r"(r[3]) : "r"(addr));
}
__device__ __forceinline__ void ldsm_x4_t(uint32_t* r, uint32_t addr)
{
    asm volatile("ldmatrix.sync.aligned.m8n8.x4.trans.shared.b16 {%0,%1,%2,%3}, [%4];"
                 : "=r"(r[0]), "=r"(r[1]), "=r"(r[2]), "=r"(r[3]) : "r"(addr));
}
__device__ __forceinline__ void mma_f16(float* c, const uint32_t* a,
                                        uint32_t b0, uint32_t b1)
{
    asm volatile(
        "mma.sync.aligned.m16n8k16.row.col.f32.f16.f16.f32 "
        "{%0,%1,%2,%3}, {%4,%5,%6,%7}, {%8,%9}, {%0,%1,%2,%3};"
        : "+f"(c[0]), "+f"(c[1]), "+f"(c[2]), "+f"(c[3])
        : "r"(a[0]), "r"(a[1]), "r"(a[2]), "r"(a[3]), "r"(b0), "r"(b1));
}
__device__ __forceinline__ uint32_t pack_f16x2(float lo, float hi)
{
    uint32_t r;
    asm("cvt.rn.f16x2.f32 %0, %1, %2;" : "=r"(r) : "f"(hi), "f"(lo));
    return r;
}

// ===========================================================================
// RoPE table kernel
// ===========================================================================
__global__ __launch_bounds__(256) void rope_table_kernel()
{
    int idx = blockIdx.x * 256 + threadIdx.x;
    if (idx >= Sq * 32) return;
    int s = idx >> 5;
    int i = idx & 31;
    double invd = exp(-(double)i * (9.210340371976184 / 32.0));
    float invf = (float)invd;
    float angf = (float)s * invf;
    double a = (double)angf;
    g_cos[idx] = (float)cos(a);
    g_sin[idx] = (float)sin(a);
}

// ===========================================================================
// Fused fp32 -> fp16 converter, 16 elems (4 float4) per thread for MLP=4.
// ===========================================================================
#define SEG_X   1048576
#define SEG_INW (SEG_X + 786432)
#define SEG_OUW (SEG_INW + 262144)
#define SEG_W1  (SEG_OUW + 1048576)
#define SEG_W2  (SEG_W1 + 1048576)

__global__ __launch_bounds__(256) void cvt_all(
    const float* __restrict__ x, const float* __restrict__ in_w,
    const float* __restrict__ out_w, const float* __restrict__ w1,
    const float* __restrict__ w2)
{
    int g = blockIdx.x * 256 + threadIdx.x;
    if (g >= SEG_W2 / 4) return;
    int idx0 = g * 4;
    const float* src;
    __half* dst;
    int base;
    if (idx0 < SEG_X)        { src = x;     dst = g_xf;            base = 0; }
    else if (idx0 < SEG_INW) { src = in_w;  dst = g_wb + OFF_INW;  base = SEG_X; }
    else if (idx0 < SEG_OUW) { src = out_w; dst = g_wb + OFF_OUTW; base = SEG_INW; }
    else if (idx0 < SEG_W1)  { src = w1;    dst = g_wb + OFF_W1;   base = SEG_OUW; }
    else                     { src = w2;    dst = g_wb + OFF_W2;   base = SEG_W1; }
    size_t off = (size_t)(idx0 - base) * 4;
    float4 v0 = *(const float4*)(src + off);
    float4 v1 = *(const float4*)(src + off + 4);
    float4 v2 = *(const float4*)(src + off + 8);
    float4 v3 = *(const float4*)(src + off + 12);
    uint4 o;
    o.x = pack_f16x2(v0.x, v0.y); o.y = pack_f16x2(v0.z, v0.w);
    o.z = pack_f16x2(v1.x, v1.y); o.w = pack_f16x2(v1.z, v1.w);
    *(uint4*)(dst + off) = o;
    o.x = pack_f16x2(v2.x, v2.y); o.y = pack_f16x2(v2.z, v2.w);
    o.z = pack_f16x2(v3.x, v3.y); o.w = pack_f16x2(v3.z, v3.w);
    *(uint4*)(dst + off + 8) = o;
}

// ===========================================================================
// fp16 GEMM, CTA 128x128 (R11 config), warp 64x32, BK=32, 3-stage pipeline.
// mode 0: fp32 out. mode 1: relu + fp16 out. mode 2: QKV + RoPE epilogue.
// ===========================================================================
#define GPITCH 80
#define GARR 10240
#define GSTG 20480

__global__ __launch_bounds__(256) void gemm_f16(
    const __half* __restrict__ A, const __half* __restrict__ W,
    const float* __restrict__ bias, float* __restrict__ Cf,
    __half* __restrict__ Ch, __half* __restrict__ Qd,
    __half* __restrict__ Kd, __half* __restrict__ Vd,
    int N, int K, int mode)
{
    extern __shared__ char dsm[];
    uint32_t sb = smem_u32(dsm);

    int tid = threadIdx.x;
    int lane = tid & 31, warp = tid >> 5;
    int wm = warp & 1;
    int wn = warp >> 1;
    int row0 = blockIdx.y * 128;
    int col0 = blockIdx.x * 128;

    float acc[4][4][4];
#pragma unroll
    for (int i = 0; i < 4; i++)
#pragma unroll
        for (int j = 0; j < 4; j++)
#pragma unroll
            for (int f = 0; f < 4; f++) acc[i][j][f] = 0.f;

    int frow = lane & 15;
    int fko  = (lane >> 4) << 3;

    const __half* gsrc[4];
    uint32_t soff[4];
#pragma unroll
    for (int i = 0; i < 4; i++) {
        int f = tid + i * 256;
        int a = f >> 9;
        int rem = f & 511;
        int r = rem >> 2, q = rem & 3;
        gsrc[i] = (a ? (W + (size_t)(col0 + r) * K)
                     : (A + (size_t)(row0 + r) * K)) + q * 8;
        soff[i] = a * GARR + r * GPITCH + q * 16;
    }

    int nk = K >> 5;

#pragma unroll
    for (int p = 0; p < 2; p++) {
        uint32_t stg = sb + p * GSTG;
#pragma unroll
        for (int i = 0; i < 4; i++)
            cp16(stg + soff[i], gsrc[i] + p * 32);
        CP_COMMIT();
    }

    int buf = 0;
    for (int t = 0; t < nk; t++) {
        if (t + 1 < nk) CP_WAIT1(); else CP_WAIT0();
        __syncthreads();
        if (t + 2 < nk) {
            int pbuf = buf + 2; if (pbuf >= 3) pbuf -= 3;
            uint32_t stg = sb + pbuf * GSTG;
            int kt = (t + 2) * 32;
#pragma unroll
            for (int i = 0; i < 4; i++)
                cp16(stg + soff[i], gsrc[i] + kt);
            CP_COMMIT();
        }

        uint32_t aA = sb + buf * GSTG;
        uint32_t aW = aA + GARR;

#pragma unroll
        for (int s = 0; s < 2; s++) {
            int ko = s * 16 + fko;
            uint32_t af[4][4], bf[2][4];
#pragma unroll
            for (int mt = 0; mt < 4; mt++) {
                int off = (wm * 64 + mt * 16 + frow) * GPITCH + ko * 2;
                ldsm_x4(af[mt], aA + off);
            }
#pragma unroll
            for (int bt = 0; bt < 2; bt++) {
                int off = (wn * 32 + bt * 16 + frow) * GPITCH + ko * 2;
                ldsm_x4(bf[bt], aW + off);
            }
#pragma unroll
            for (int mt = 0; mt < 4; mt++)
#pragma unroll
                for (int bt = 0; bt < 2; bt++)
#pragma unroll
                    for (int h = 0; h < 2; h++) {
                        int nt = bt * 2 + h;
                        mma_f16(acc[mt][nt], af[mt], bf[bt][h], bf[bt][h + 2]);
                    }
        }
        if (++buf == 3) buf = 0;
    }

    int tr = lane >> 2, tc = (lane & 3) * 2;
#pragma unroll
    for (int mt = 0; mt < 4; mt++) {
#pragma unroll
        for (int nt = 0; nt < 4; nt++) {
            int col = col0 + wn * 32 + nt * 8 + tc;
            float2 bv = *(const float2*)(bias + col);
            int r0 = row0 + wm * 64 + mt * 16 + tr;
            float o[4];
            o[0] = acc[mt][nt][0] + bv.x;
            o[1] = acc[mt][nt][1] + bv.y;
            o[2] = acc[mt][nt][2] + bv.x;
            o[3] = acc[mt][nt][3] + bv.y;
            if (mode == 0) {
                *(float2*)(Cf + (size_t)r0 * N + col) = make_float2(o[0], o[1]);
                *(float2*)(Cf + (size_t)(r0 + 8) * N + col) = make_float2(o[2], o[3]);
            } else if (mode == 1) {
#pragma unroll
                for (int i = 0; i < 4; i++) o[i] = fmaxf(o[i], 0.f);
                *(uint32_t*)(Ch + (size_t)r0 * N + col) = pack_f16x2(o[0], o[1]);
                *(uint32_t*)(Ch + (size_t)(r0 + 8) * N + col) = pack_f16x2(o[2], o[3]);
            } else {
                int sector = col >> 10;
                int cc = col & 1023;
                int h = cc >> 6;
                int e = cc & 63;
                int i = e >> 1;
#pragma unroll
                for (int rg = 0; rg < 2; rg++) {
                    int r = r0 + rg * 8;
                    int s = r & (Sq - 1);
                    int b = r >> 11;
                    float v0 = o[rg * 2], v1 = o[rg * 2 + 1];
                    if (sector < 2) {
                        float c = g_cos[s * 32 + i];
                        float sn = g_sin[s * 32 + i];
                        float re = v0 * c - v1 * sn;
                        float ro = v0 * sn + v1 * c;
                        v0 = re; v1 = ro;
                    }
                    __half* dst = (sector == 0) ? Qd : (sector == 1) ? Kd : Vd;
                    size_t d = ((size_t)(b * Hh + h) * Sq + s) * 64 + e;
                    *(uint32_t*)(dst + d) = pack_f16x2(v0, v1);
                }
            }
        }
    }
}

// ===========================================================================
// Flash attention, pure fp16, 3-stage cp.async K/V pipeline.
// Softmax in base-2: one FFMA + MUFU.EX2 per element (scale folded).
// ===========================================================================
#define APITCH 144
#define AQ0 0
#define AKV0 18432
#define AARR 9216
#define KVSTG 18432
#define ATT_SMEM 73728
#define SC2 0.1803368801111244f   // 0.125 * log2(e)

__global__ __launch_bounds__(256) void attn_mma(
    const __half* __restrict__ Qq, const __half* __restrict__ Kk,
    const __half* __restrict__ Vv, __half* __restrict__ at)
{
    extern __shared__ char dsm[];
    uint32_t sb = smem_u32(dsm);

    int tid = threadIdx.x;
    int lane = tid & 31, warp = tid >> 5;
    int bh = blockIdx.y;
    int b = bh >> 4, hh = bh & 15;
    int q0 = blockIdx.x * 128;

    size_t hbase = (size_t)bh * Sq * 64;

    const __half* kvsrc[4];
    uint32_t kvoff[4];
#pragma unroll
    for (int i = 0; i < 4; i++) {
        int f = tid + i * 256;
        int a = f >> 9, rem = f & 511, r = rem >> 3, q = rem & 7;
        kvsrc[i] = (a ? Vv : Kk) + hbase + (size_t)r * 64 + q * 8;
        kvoff[i] = a * AARR + r * APITCH + q * 16;
    }

#pragma unroll
    for (int i = 0; i < 4; i++) {
        int f = tid + i * 256;
        int r = f >> 3, q = f & 7;
        cp16(sb + AQ0 + r * APITCH + q * 16,
             Qq + hbase + (size_t)(q0 + r) * 64 + q * 8);
    }
#pragma unroll
    for (int i = 0; i < 4; i++)
        cp16(sb + AKV0 + kvoff[i], kvsrc[i]);
    CP_COMMIT();
#pragma unroll
    for (int i = 0; i < 4; i++)
        cp16(sb + AKV0 + KVSTG + kvoff[i], kvsrc[i] + (size_t)64 * 64);
    CP_COMMIT();

    int frow = lane & 15;
    int fko  = (lane >> 4) << 3;

    uint32_t aQ[4][4];
    float m0 = -1e30f, m1 = -1e30f, l0 = 0.f, l1 = 0.f;  // m in base-2 units
    float oacc[8][4];
#pragma unroll
    for (int j = 0; j < 8; j++)
#pragma unroll
        for (int f = 0; f < 4; f++) oacc[j][f] = 0.f;

    const int NT = Sq / 64;
    int buf = 0;
    for (int t = 0; t < NT; t++) {
        if (t + 1 < NT) CP_WAIT1(); else CP_WAIT0();
        __syncthreads();
        if (t + 2 < NT) {
            int pbuf = buf + 2; if (pbuf >= 3) pbuf -= 3;
            uint32_t stg = sb + AKV0 + pbuf * KVSTG;
            size_t kofs = (size_t)(t + 2) * 64 * 64;
#pragma unroll
            for (int i = 0; i < 4; i++)
                cp16(stg + kvoff[i], kvsrc[i] + kofs);
            CP_COMMIT();
        }

        if (t == 0) {
#pragma unroll
            for (int c = 0; c < 4; c++) {
                int off = (warp * 16 + frow) * APITCH + (c * 16 + fko) * 2;
                ldsm_x4(aQ[c], sb + AQ0 + off);
            }
        }

        uint32_t aKB = sb + AKV0 + buf * KVSTG;
        uint32_t aVB = aKB + AARR;

        float sacc[8][4];
#pragma unroll
        for (int j = 0; j < 8; j++)
#pragma unroll
            for (int f = 0; f < 4; f++) sacc[j][f] = 0.f;

#pragma unroll
        for (int kd = 0; kd < 4; kd++) {
#pragma unroll
            for (int bt = 0; bt < 4; bt++) {
                uint32_t kf[4];
                int off = (bt * 16 + frow) * APITCH + (kd * 16 + fko) * 2;
                ldsm_x4(kf, aKB + off);
#pragma unroll
                for (int h = 0; h < 2; h++) {
                    int nt = bt * 2 + h;
                    mma_f16(sacc[nt], aQ[kd], kf[h], kf[h + 2]);
                }
            }
        }

        float rmax0 = -1e30f, rmax1 = -1e30f;
#pragma unroll
        for (int j = 0; j < 8; j++) {
            rmax0 = fmaxf(rmax0, fmaxf(sacc[j][0], sacc[j][1]));
            rmax1 = fmaxf(rmax1, fmaxf(sacc[j][2], sacc[j][3]));
        }
        rmax0 = fmaxf(rmax0, __shfl_xor_sync(0xffffffffu, rmax0, 1));
        rmax0 = fmaxf(rmax0, __shfl_xor_sync(0xffffffffu, rmax0, 2));
        rmax1 = fmaxf(rmax1, __shfl_xor_sync(0xffffffffu, rmax1, 1));
        rmax1 = fmaxf(rmax1, __shfl_xor_sync(0xffffffffu, rmax1, 2));

        float mn0 = fmaxf(m0, rmax0 * SC2);
        float mn1 = fmaxf(m1, rmax1 * SC2);
        float corr0 = exp2f(m0 - mn0);
        float corr1 = exp2f(m1 - mn1);
        m0 = mn0; m1 = mn1;

        uint32_t pah[4][4];
        float ps0 = 0.f, ps1 = 0.f;
#pragma unroll
        for (int c = 0; c < 4; c++) {
#pragma unroll
            for (int u = 0; u < 2; u++) {
                int j = 2 * c + u;
                float p0 = exp2f(fmaf(sacc[j][0], SC2, -mn0));
                float p1 = exp2f(fmaf(sacc[j][1], SC2, -mn0));
                float p2 = exp2f(fmaf(sacc[j][2], SC2, -mn1));
                float p3 = exp2f(fmaf(sacc[j][3], SC2, -mn1));
                ps0 += p0 + p1;
                ps1 += p2 + p3;
                pah[c][2 * u + 0] = pack_f16x2(p0, p1);
                pah[c][2 * u + 1] = pack_f16x2(p2, p3);
            }
        }
        ps0 += __shfl_xor_sync(0xffffffffu, ps0, 1);
        ps0 += __shfl_xor_sync(0xffffffffu, ps0, 2);
        ps1 += __shfl_xor_sync(0xffffffffu, ps1, 1);
        ps1 += __shfl_xor_sync(0xffffffffu, ps1, 2);
        l0 = l0 * corr0 + ps0;
        l1 = l1 * corr1 + ps1;

#pragma unroll
        for (int j = 0; j < 8; j++) {
            oacc[j][0] *= corr0; oacc[j][1] *= corr0;
            oacc[j][2] *= corr1; oacc[j][3] *= corr1;
        }

#pragma unroll
        for (int c = 0; c < 4; c++) {
#pragma unroll
            for (int g = 0; g < 4; g++) {
                uint32_t vf[4];
                int off = (c * 16 + frow) * APITCH + (g * 16 + fko) * 2;
                ldsm_x4_t(vf, aVB + off);
#pragma unroll
                for (int h2 = 0; h2 < 2; h2++) {
                    int j = g * 2 + h2;
                    mma_f16(oacc[j], pah[c], vf[2 * h2], vf[2 * h2 + 1]);
                }
            }
        }
        if (++buf == 3) buf = 0;
    }

    float inv0 = 1.f / l0, inv1 = 1.f / l1;
    int tr = lane >> 2, tc = (lane & 3) * 2;
    int row0 = b * Sq + q0 + warp * 16 + tr;
#pragma unroll
    for (int j = 0; j < 8; j++) {
        int col = hh * 64 + j * 8 + tc;
        *(uint32_t*)(at + (size_t)row0 * Dm + col) =
            pack_f16x2(oacc[j][0] * inv0, oacc[j][1] * inv0);
        *(uint32_t*)(at + (size_t)(row0 + 8) * Dm + col) =
            pack_f16x2(oacc[j][2] * inv1, oacc[j][3] * inv1);
    }
}

// ===========================================================================
// Fused residual add + LayerNorm (+ optional fp16 output)
// ===========================================================================
__device__ __forceinline__ float block_allreduce(float v, float* sred)
{
#pragma unroll
    for (int o = 16; o; o >>= 1) v += __shfl_xor_sync(0xffffffffu, v, o);
    int w = threadIdx.x >> 5;
    if ((threadIdx.x & 31) == 0) sred[w] = v;
    __syncthreads();
    float t = (threadIdx.x < 8) ? sred[threadIdx.x] : 0.f;
    if (threadIdx.x < 32) {
#pragma unroll
        for (int o = 4; o; o >>= 1) t += __shfl_xor_sync(0xffffffffu, t, o);
        if (threadIdx.x == 0) sred[0] = t;
    }
    __syncthreads();
    float r = sred[0];
    __syncthreads();
    return r;
}

__global__ __launch_bounds__(256) void add_ln_kernel(
    const float* __restrict__ x, const float* __restrict__ y,
    const float* __restrict__ g, const float* __restrict__ bta,
    float* __restrict__ out, __half* __restrict__ oh)
{
    __shared__ float sred[8];
    int row = blockIdx.x;
    int tid = threadIdx.x;
    const float* xr = x + (size_t)row * Dm;
    const float* yr = y + (size_t)row * Dm;

    float4 xv = *(const float4*)(xr + tid * 4);
    float4 yv = *(const float4*)(yr + tid * 4);
    float v[4] = {xv.x + yv.x, xv.y + yv.y, xv.z + yv.z, xv.w + yv.w};

    float sum = v[0] + v[1] + v[2] + v[3];
    sum = block_allreduce(sum, sred);
    float mean = sum * (1.f / (float)Dm);

    float sq = 0.f;
#pragma unroll
    for (int i = 0; i < 4; i++) {
        float d = v[i] - mean;
        sq += d * d;
    }
    sq = block_allreduce(sq, sred);
    float inv = rsqrtf(sq * (1.f / (float)Dm) + 1e-5f);

    float4 gv = *(const float4*)(g + tid * 4);
    float4 bv = *(const float4*)(bta + tid * 4);
    float o[4];
    o[0] = (v[0] - mean) * inv * gv.x + bv.x;
    o[1] = (v[1] - mean) * inv * gv.y + bv.y;
    o[2] = (v[2] - mean) * inv * gv.z + bv.z;
    o[3] = (v[3] - mean) * inv * gv.w + bv.w;
    *(float4*)(out + (size_t)row * Dm + tid * 4) =
        make_float4(o[0], o[1], o[2], o[3]);

    if (oh) {
        uint2 hv;
        hv.x = pack_f16x2(o[0], o[1]);
        hv.y = pack_f16x2(o[2], o[3]);
        *(uint2*)(oh + (size_t)row * Dm + tid * 4) = hv;
    }
}

// ===========================================================================
extern "C" void kernel_launch(void* const* d_in, const int* in_sizes, int n_in,
                              void* d_out, int out_size)
{
    const float* x     = (const float*)d_in[0];
    const float* in_w  = (const float*)d_in[1];
    const float* in_b  = (const float*)d_in[2];
    const float* out_w = (const float*)d_in[3];
    const float* out_b = (const float*)d_in[4];
    const float* w1    = (const float*)d_in[5];
    const float* b1    = (const float*)d_in[6];
    const float* w2    = (const float*)d_in[7];
    const float* b2    = (const float*)d_in[8];
    const float* ln1g  = (const float*)d_in[9];
    const float* ln1b  = (const float*)d_in[10];
    const float* ln2g  = (const float*)d_in[11];
    const float* ln2b  = (const float*)d_in[12];
    float* out = (float*)d_out;

    float *tmp, *hbuf;
    __half *xf, *wb, *qq, *kk, *vv, *at, *hf, *ff;
    cudaGetSymbolAddress((void**)&tmp, g_tmp);
    cudaGetSymbolAddress((void**)&hbuf, g_h);
    cudaGetSymbolAddress((void**)&xf, g_xf);
    cudaGetSymbolAddress((void**)&wb, g_wb);
    cudaGetSymbolAddress((void**)&qq, g_qq);
    cudaGetSymbolAddress((void**)&kk, g_kk);
    cudaGetSymbolAddress((void**)&vv, g_vv);
    cudaGetSymbolAddress((void**)&at, g_at);
    cudaGetSymbolAddress((void**)&hf, g_hf);
    cudaGetSymbolAddress((void**)&ff, g_ff);

    cudaFuncSetAttribute(gemm_f16, cudaFuncAttributeMaxDynamicSharedMemorySize,
                         3 * GSTG);
    cudaFuncSetAttribute(attn_mma, cudaFuncAttributeMaxDynamicSharedMemorySize,
                         ATT_SMEM);

    dim3 tb(256);

    rope_table_kernel<<<(Sq * 32 + 255) / 256, tb>>>();
    cvt_all<<<(SEG_W2 / 4 + 255) / 256, tb>>>(x, in_w, out_w, w1, w2);

    // QKV projection + fused RoPE -> head-major fp16 Q/K/V
    gemm_f16<<<dim3(3072 / 128, Mrows / 128), tb, 3 * GSTG>>>(
        xf, wb + OFF_INW, in_b, nullptr, nullptr, qq, kk, vv, 3 * Dm, Dm, 2);
    // Attention -> fp16
    attn_mma<<<dim3(Sq / 128, Bq * Hh), tb, ATT_SMEM>>>(qq, kk, vv, at);
    // Output projection -> fp32
    gemm_f16<<<dim3(Dm / 128, Mrows / 128), tb, 3 * GSTG>>>(
        at, wb + OFF_OUTW, out_b, tmp, nullptr, nullptr, nullptr, nullptr,
        Dm, Dm, 0);
    // LN1 -> fp32 h + fp16
    add_ln_kernel<<<Mrows, tb>>>(x, tmp, ln1g, ln1b, hbuf, hf);
    // FF1 + ReLU -> fp16
    gemm_f16<<<dim3(Ff / 128, Mrows / 128), tb, 3 * GSTG>>>(
        hf, wb + OFF_W1, b1, nullptr, ff, nullptr, nullptr, nullptr,
        Ff, Dm, 1);
    // FF2 -> fp32
    gemm_f16<<<dim3(Dm / 128, Mrows / 128), tb, 3 * GSTG>>>(
        ff, wb + OFF_W2, b2, tmp, nullptr, nullptr, nullptr, nullptr,
        Dm, Ff, 0);
    // LN2 -> out
    add_ln_kernel<<<Mrows, tb>>>(hbuf, tmp, ln2g, ln2b, out, nullptr);
}

// round 14
// speedup vs baseline: 1.1727x; 1.0719x over previous
#include <cuda_runtime.h>
#include <cuda_fp16.h>
#include <math.h>
#include <stdint.h>

// Problem constants
#define Bq 2
#define Sq 2048
#define Dm 1024
#define Ff 4096
#define Hh 16
#define Dhd 64
#define Mrows 4096  // B*S

// ---------------------------------------------------------------------------
// Scratch (device globals)
// ---------------------------------------------------------------------------
__device__ float g_tmp[(size_t)Mrows * Dm];
__device__ float g_h[(size_t)Mrows * Dm];
__device__ float g_cos[Sq * 32];
__device__ float g_sin[Sq * 32];

__device__ __half g_xf[(size_t)Mrows * Dm];
__device__ __half g_wb[12582912];
#define OFF_INW 0
#define OFF_OUTW 3145728
#define OFF_W1 4194304
#define OFF_W2 8388608
__device__ __half g_qq[(size_t)Bq * Hh * Sq * 64];
__device__ __half g_kk[(size_t)Bq * Hh * Sq * 64];
__device__ __half g_vv[(size_t)Bq * Hh * Sq * 64];
__device__ __half g_at[(size_t)Mrows * Dm];
__device__ __half g_hf[(size_t)Mrows * Dm];
__device__ __half g_ff[(size_t)Mrows * Ff];

__device__ __forceinline__ uint32_t smem_u32(const void* p) {
    uint32_t a;
    asm("{ .reg .u64 t; cvta.to.shared.u64 t, %1; cvt.u32.u64 %0, t; }"
        : "=r"(a) : "l"(p));
    return a;
}
__device__ __forceinline__ void cp16(uint32_t dst, const void* src) {
    asm volatile("cp.async.cg.shared.global [%0], [%1], 16;"
                 :: "r"(dst), "l"(src));
}
#define CP_COMMIT() asm volatile("cp.async.commit_group;" ::: "memory")
#define CP_WAIT1()  asm volatile("cp.async.wait_group 1;" ::: "memory")
#define CP_WAIT0()  asm volatile("cp.async.wait_group 0;" ::: "memory")

__device__ __forceinline__ void ldsm_x4(uint32_t* r, uint32_t addr)
{
    asm volatile("ldmatrix.sync.aligned.m8n8.x4.shared.b16 {%0,%1,%2,%3}, [%4];"
                 : "=r"(r[0]), "=r"(r[1]), "=r"(r[2]), "=r"(r[3]) : "r"(addr));
}
__device__ __forceinline__ void ldsm_x4_t(uint32_t* r, uint32_t addr)
{
    asm volatile("ldmatrix.sync.aligned.m8n8.x4.trans.shared.b16 {%0,%1,%2,%3}, [%4];"
                 : "=r"(r[0]), "=r"(r[1]), "=r"(r[2]), "=r"(r[3]) : "r"(addr));
}
__device__ __forceinline__ void mma_f16(float* c, const uint32_t* a,
                                        uint32_t b0, uint32_t b1)
{
    asm volatile(
        "mma.sync.aligned.m16n8k16.row.col.f32.f16.f16.f32 "
        "{%0,%1,%2,%3}, {%4,%5,%6,%7}, {%8,%9}, {%0,%1,%2,%3};"
        : "+f"(c[0]), "+f"(c[1]), "+f"(c[2]), "+f"(c[3])
        : "r"(a[0]), "r"(a[1]), "r"(a[2]), "r"(a[3]), "r"(b0), "r"(b1));
}
__device__ __forceinline__ uint32_t pack_f16x2(float lo, float hi)
{
    uint32_t r;
    asm("cvt.rn.f16x2.f32 %0, %1, %2;" : "=r"(r) : "f"(hi), "f"(lo));
    return r;
}

// ===========================================================================
// RoPE table kernel
// ===========================================================================
__global__ __launch_bounds__(256) void rope_table_kernel()
{
    int idx = blockIdx.x * 256 + threadIdx.x;
    if (idx >= Sq * 32) return;
    int s = idx >> 5;
    int i = idx & 31;
    double invd = exp(-(double)i * (9.210340371976184 / 32.0));
    float invf = (float)invd;
    float angf = (float)s * invf;
    double a = (double)angf;
    g_cos[idx] = (float)cos(a);
    g_sin[idx] = (float)sin(a);
}

// ===========================================================================
// Fused fp32 -> fp16 converter, 16 elems (4 float4) per thread for MLP=4.
// ===========================================================================
#define SEG_X   1048576
#define SEG_INW (SEG_X + 786432)
#define SEG_OUW (SEG_INW + 262144)
#define SEG_W1  (SEG_OUW + 1048576)
#define SEG_W2  (SEG_W1 + 1048576)

__global__ __launch_bounds__(256) void cvt_all(
    const float* __restrict__ x, const float* __restrict__ in_w,
    const float* __restrict__ out_w, const float* __restrict__ w1,
    const float* __restrict__ w2)
{
    int g = blockIdx.x * 256 + threadIdx.x;
    if (g >= SEG_W2 / 4) return;
    int idx0 = g * 4;
    const float* src;
    __half* dst;
    int base;
    if (idx0 < SEG_X)        { src = x;     dst = g_xf;            base = 0; }
    else if (idx0 < SEG_INW) { src = in_w;  dst = g_wb + OFF_INW;  base = SEG_X; }
    else if (idx0 < SEG_OUW) { src = out_w; dst = g_wb + OFF_OUTW; base = SEG_INW; }
    else if (idx0 < SEG_W1)  { src = w1;    dst = g_wb + OFF_W1;   base = SEG_OUW; }
    else                     { src = w2;    dst = g_wb + OFF_W2;   base = SEG_W1; }
    size_t off = (size_t)(idx0 - base) * 4;
    float4 v0 = *(const float4*)(src + off);
    float4 v1 = *(const float4*)(src + off + 4);
    float4 v2 = *(const float4*)(src + off + 8);
    float4 v3 = *(const float4*)(src + off + 12);
    uint4 o;
    o.x = pack_f16x2(v0.x, v0.y); o.y = pack_f16x2(v0.z, v0.w);
    o.z = pack_f16x2(v1.x, v1.y); o.w = pack_f16x2(v1.z, v1.w);
    *(uint4*)(dst + off) = o;
    o.x = pack_f16x2(v2.x, v2.y); o.y = pack_f16x2(v2.z, v2.w);
    o.z = pack_f16x2(v3.x, v3.y); o.w = pack_f16x2(v3.z, v3.w);
    *(uint4*)(dst + off + 8) = o;
}

// ===========================================================================
// fp16 GEMM, CTA 128x128, warp 64x32, BK=64, 3-stage cp.async pipeline.
// pitch 144B (9x16B, conflict-free). smem/stage: 2 x 128 x 144 = 36864 B,
// x3 stages = 110592 B -> 2 CTAs/SM. 64 MMAs/warp between barriers.
// mode 0: fp32 out. mode 1: relu + fp16 out. mode 2: QKV + RoPE epilogue.
// ===========================================================================
#define GPITCH 144
#define GARR 18432
#define GSTG 36864

__global__ __launch_bounds__(256, 2) void gemm_f16(
    const __half* __restrict__ A, const __half* __restrict__ W,
    const float* __restrict__ bias, float* __restrict__ Cf,
    __half* __restrict__ Ch, __half* __restrict__ Qd,
    __half* __restrict__ Kd, __half* __restrict__ Vd,
    int N, int K, int mode)
{
    extern __shared__ char dsm[];
    uint32_t sb = smem_u32(dsm);

    int tid = threadIdx.x;
    int lane = tid & 31, warp = tid >> 5;
    int wm = warp & 1;
    int wn = warp >> 1;
    int row0 = blockIdx.y * 128;
    int col0 = blockIdx.x * 128;

    float acc[4][4][4];
#pragma unroll
    for (int i = 0; i < 4; i++)
#pragma unroll
        for (int j = 0; j < 4; j++)
#pragma unroll
            for (int f = 0; f < 4; f++) acc[i][j][f] = 0.f;

    int frow = lane & 15;
    int fko  = (lane >> 4) << 3;

    // staging map: 2048 16B-chunks per stage (A 1024 + W 1024), 8 per thread
    const __half* gsrc[8];
    uint32_t soff[8];
#pragma unroll
    for (int i = 0; i < 8; i++) {
        int f = tid + i * 256;
        int a = f >> 10;
        int rem = f & 1023;
        int r = rem >> 3, q = rem & 7;
        gsrc[i] = (a ? (W + (size_t)(col0 + r) * K)
                     : (A + (size_t)(row0 + r) * K)) + q * 8;
        soff[i] = a * GARR + r * GPITCH + q * 16;
    }

    int nk = K >> 6;

    // prologue: tiles 0, 1
#pragma unroll
    for (int p = 0; p < 2; p++) {
        uint32_t stg = sb + p * GSTG;
#pragma unroll
        for (int i = 0; i < 8; i++)
            cp16(stg + soff[i], gsrc[i] + p * 64);
        CP_COMMIT();
    }

    int buf = 0;
    for (int t = 0; t < nk; t++) {
        if (t + 1 < nk) CP_WAIT1(); else CP_WAIT0();
        __syncthreads();
        if (t + 2 < nk) {
            int pbuf = buf + 2; if (pbuf >= 3) pbuf -= 3;
            uint32_t stg = sb + pbuf * GSTG;
            int kt = (t + 2) * 64;
#pragma unroll
            for (int i = 0; i < 8; i++)
                cp16(stg + soff[i], gsrc[i] + kt);
            CP_COMMIT();
        }

        uint32_t aA = sb + buf * GSTG;
        uint32_t aW = aA + GARR;

#pragma unroll
        for (int s = 0; s < 4; s++) {
            int ko = s * 16 + fko;
            uint32_t af[4][4], bf[2][4];
#pragma unroll
            for (int mt = 0; mt < 4; mt++) {
                int off = (wm * 64 + mt * 16 + frow) * GPITCH + ko * 2;
                ldsm_x4(af[mt], aA + off);
            }
#pragma unroll
            for (int bt = 0; bt < 2; bt++) {
                int off = (wn * 32 + bt * 16 + frow) * GPITCH + ko * 2;
                ldsm_x4(bf[bt], aW + off);
            }
#pragma unroll
            for (int mt = 0; mt < 4; mt++)
#pragma unroll
                for (int bt = 0; bt < 2; bt++)
#pragma unroll
                    for (int h = 0; h < 2; h++) {
                        int nt = bt * 2 + h;
                        mma_f16(acc[mt][nt], af[mt], bf[bt][h], bf[bt][h + 2]);
                    }
        }
        if (++buf == 3) buf = 0;
    }

    int tr = lane >> 2, tc = (lane & 3) * 2;
#pragma unroll
    for (int mt = 0; mt < 4; mt++) {
#pragma unroll
        for (int nt = 0; nt < 4; nt++) {
            int col = col0 + wn * 32 + nt * 8 + tc;
            float2 bv = *(const float2*)(bias + col);
            int r0 = row0 + wm * 64 + mt * 16 + tr;
            float o[4];
            o[0] = acc[mt][nt][0] + bv.x;
            o[1] = acc[mt][nt][1] + bv.y;
            o[2] = acc[mt][nt][2] + bv.x;
            o[3] = acc[mt][nt][3] + bv.y;
            if (mode == 0) {
                *(float2*)(Cf + (size_t)r0 * N + col) = make_float2(o[0], o[1]);
                *(float2*)(Cf + (size_t)(r0 + 8) * N + col) = make_float2(o[2], o[3]);
            } else if (mode == 1) {
#pragma unroll
                for (int i = 0; i < 4; i++) o[i] = fmaxf(o[i], 0.f);
                *(uint32_t*)(Ch + (size_t)r0 * N + col) = pack_f16x2(o[0], o[1]);
                *(uint32_t*)(Ch + (size_t)(r0 + 8) * N + col) = pack_f16x2(o[2], o[3]);
            } else {
                int sector = col >> 10;
                int cc = col & 1023;
                int h = cc >> 6;
                int e = cc & 63;
                int i = e >> 1;
#pragma unroll
                for (int rg = 0; rg < 2; rg++) {
                    int r = r0 + rg * 8;
                    int s = r & (Sq - 1);
                    int b = r >> 11;
                    float v0 = o[rg * 2], v1 = o[rg * 2 + 1];
                    if (sector < 2) {
                        float c = g_cos[s * 32 + i];
                        float sn = g_sin[s * 32 + i];
                        float re = v0 * c - v1 * sn;
                        float ro = v0 * sn + v1 * c;
                        v0 = re; v1 = ro;
                    }
                    __half* dst = (sector == 0) ? Qd : (sector == 1) ? Kd : Vd;
                    size_t d = ((size_t)(b * Hh + h) * Sq + s) * 64 + e;
                    *(uint32_t*)(dst + d) = pack_f16x2(v0, v1);
                }
            }
        }
    }
}

// ===========================================================================
// Flash attention, pure fp16, 3-stage cp.async K/V pipeline (R13 config).
// Softmax in base-2: one FFMA + MUFU.EX2 per element.
// ===========================================================================
#define APITCH 144
#define AQ0 0
#define AKV0 18432
#define AARR 9216
#define KVSTG 18432
#define ATT_SMEM 73728
#define SC2 0.1803368801111244f   // 0.125 * log2(e)

__global__ __launch_bounds__(256) void attn_mma(
    const __half* __restrict__ Qq, const __half* __restrict__ Kk,
    const __half* __restrict__ Vv, __half* __restrict__ at)
{
    extern __shared__ char dsm[];
    uint32_t sb = smem_u32(dsm);

    int tid = threadIdx.x;
    int lane = tid & 31, warp = tid >> 5;
    int bh = blockIdx.y;
    int b = bh >> 4, hh = bh & 15;
    int q0 = blockIdx.x * 128;

    size_t hbase = (size_t)bh * Sq * 64;

    const __half* kvsrc[4];
    uint32_t kvoff[4];
#pragma unroll
    for (int i = 0; i < 4; i++) {
        int f = tid + i * 256;
        int a = f >> 9, rem = f & 511, r = rem >> 3, q = rem & 7;
        kvsrc[i] = (a ? Vv : Kk) + hbase + (size_t)r * 64 + q * 8;
        kvoff[i] = a * AARR + r * APITCH + q * 16;
    }

#pragma unroll
    for (int i = 0; i < 4; i++) {
        int f = tid + i * 256;
        int r = f >> 3, q = f & 7;
        cp16(sb + AQ0 + r * APITCH + q * 16,
             Qq + hbase + (size_t)(q0 + r) * 64 + q * 8);
    }
#pragma unroll
    for (int i = 0; i < 4; i++)
        cp16(sb + AKV0 + kvoff[i], kvsrc[i]);
    CP_COMMIT();
#pragma unroll
    for (int i = 0; i < 4; i++)
        cp16(sb + AKV0 + KVSTG + kvoff[i], kvsrc[i] + (size_t)64 * 64);
    CP_COMMIT();

    int frow = lane & 15;
    int fko  = (lane >> 4) << 3;

    uint32_t aQ[4][4];
    float m0 = -1e30f, m1 = -1e30f, l0 = 0.f, l1 = 0.f;
    float oacc[8][4];
#pragma unroll
    for (int j = 0; j < 8; j++)
#pragma unroll
        for (int f = 0; f < 4; f++) oacc[j][f] = 0.f;

    const int NT = Sq / 64;
    int buf = 0;
    for (int t = 0; t < NT; t++) {
        if (t + 1 < NT) CP_WAIT1(); else CP_WAIT0();
        __syncthreads();
        if (t + 2 < NT) {
            int pbuf = buf + 2; if (pbuf >= 3) pbuf -= 3;
            uint32_t stg = sb + AKV0 + pbuf * KVSTG;
            size_t kofs = (size_t)(t + 2) * 64 * 64;
#pragma unroll
            for (int i = 0; i < 4; i++)
                cp16(stg + kvoff[i], kvsrc[i] + kofs);
            CP_COMMIT();
        }

        if (t == 0) {
#pragma unroll
            for (int c = 0; c < 4; c++) {
                int off = (warp * 16 + frow) * APITCH + (c * 16 + fko) * 2;
                ldsm_x4(aQ[c], sb + AQ0 + off);
            }
        }

        uint32_t aKB = sb + AKV0 + buf * KVSTG;
        uint32_t aVB = aKB + AARR;

        float sacc[8][4];
#pragma unroll
        for (int j = 0; j < 8; j++)
#pragma unroll
            for (int f = 0; f < 4; f++) sacc[j][f] = 0.f;

#pragma unroll
        for (int kd = 0; kd < 4; kd++) {
#pragma unroll
            for (int bt = 0; bt < 4; bt++) {
                uint32_t kf[4];
                int off = (bt * 16 + frow) * APITCH + (kd * 16 + fko) * 2;
                ldsm_x4(kf, aKB + off);
#pragma unroll
                for (int h = 0; h < 2; h++) {
                    int nt = bt * 2 + h;
                    mma_f16(sacc[nt], aQ[kd], kf[h], kf[h + 2]);
                }
            }
        }

        float rmax0 = -1e30f, rmax1 = -1e30f;
#pragma unroll
        for (int j = 0; j < 8; j++) {
            rmax0 = fmaxf(rmax0, fmaxf(sacc[j][0], sacc[j][1]));
            rmax1 = fmaxf(rmax1, fmaxf(sacc[j][2], sacc[j][3]));
        }
        rmax0 = fmaxf(rmax0, __shfl_xor_sync(0xffffffffu, rmax0, 1));
        rmax0 = fmaxf(rmax0, __shfl_xor_sync(0xffffffffu, rmax0, 2));
        rmax1 = fmaxf(rmax1, __shfl_xor_sync(0xffffffffu, rmax1, 1));
        rmax1 = fmaxf(rmax1, __shfl_xor_sync(0xffffffffu, rmax1, 2));

        float mn0 = fmaxf(m0, rmax0 * SC2);
        float mn1 = fmaxf(m1, rmax1 * SC2);
        float corr0 = exp2f(m0 - mn0);
        float corr1 = exp2f(m1 - mn1);
        m0 = mn0; m1 = mn1;

        uint32_t pah[4][4];
        float ps0 = 0.f, ps1 = 0.f;
#pragma unroll
        for (int c = 0; c < 4; c++) {
#pragma unroll
            for (int u = 0; u < 2; u++) {
                int j = 2 * c + u;
                float p0 = exp2f(fmaf(sacc[j][0], SC2, -mn0));
                float p1 = exp2f(fmaf(sacc[j][1], SC2, -mn0));
                float p2 = exp2f(fmaf(sacc[j][2], SC2, -mn1));
                float p3 = exp2f(fmaf(sacc[j][3], SC2, -mn1));
                ps0 += p0 + p1;
                ps1 += p2 + p3;
                pah[c][2 * u + 0] = pack_f16x2(p0, p1);
                pah[c][2 * u + 1] = pack_f16x2(p2, p3);
            }
        }
        ps0 += __shfl_xor_sync(0xffffffffu, ps0, 1);
        ps0 += __shfl_xor_sync(0xffffffffu, ps0, 2);
        ps1 += __shfl_xor_sync(0xffffffffu, ps1, 1);
        ps1 += __shfl_xor_sync(0xffffffffu, ps1, 2);
        l0 = l0 * corr0 + ps0;
        l1 = l1 * corr1 + ps1;

#pragma unroll
        for (int j = 0; j < 8; j++) {
            oacc[j][0] *= corr0; oacc[j][1] *= corr0;
            oacc[j][2] *= corr1; oacc[j][3] *= corr1;
        }

#pragma unroll
        for (int c = 0; c < 4; c++) {
#pragma unroll
            for (int g = 0; g < 4; g++) {
                uint32_t vf[4];
                int off = (c * 16 + frow) * APITCH + (g * 16 + fko) * 2;
                ldsm_x4_t(vf, aVB + off);
#pragma unroll
                for (int h2 = 0; h2 < 2; h2++) {
                    int j = g * 2 + h2;
                    mma_f16(oacc[j], pah[c], vf[2 * h2], vf[2 * h2 + 1]);
                }
            }
        }
        if (++buf == 3) buf = 0;
    }

    float inv0 = 1.f / l0, inv1 = 1.f / l1;
    int tr = lane >> 2, tc = (lane & 3) * 2;
    int row0 = b * Sq + q0 + warp * 16 + tr;
#pragma unroll
    for (int j = 0; j < 8; j++) {
        int col = hh * 64 + j * 8 + tc;
        *(uint32_t*)(at + (size_t)row0 * Dm + col) =
            pack_f16x2(oacc[j][0] * inv0, oacc[j][1] * inv0);
        *(uint32_t*)(at + (size_t)(row0 + 8) * Dm + col) =
            pack_f16x2(oacc[j][2] * inv1, oacc[j][3] * inv1);
    }
}

// ===========================================================================
// Fused residual add + LayerNorm (+ optional fp16 output)
// ===========================================================================
__device__ __forceinline__ float block_allreduce(float v, float* sred)
{
#pragma unroll
    for (int o = 16; o; o >>= 1) v += __shfl_xor_sync(0xffffffffu, v, o);
    int w = threadIdx.x >> 5;
    if ((threadIdx.x & 31) == 0) sred[w] = v;
    __syncthreads();
    float t = (threadIdx.x < 8) ? sred[threadIdx.x] : 0.f;
    if (threadIdx.x < 32) {
#pragma unroll
        for (int o = 4; o; o >>= 1) t += __shfl_xor_sync(0xffffffffu, t, o);
        if (threadIdx.x == 0) sred[0] = t;
    }
    __syncthreads();
    float r = sred[0];
    __syncthreads();
    return r;
}

__global__ __launch_bounds__(256) void add_ln_kernel(
    const float* __restrict__ x, const float* __restrict__ y,
    const float* __restrict__ g, const float* __restrict__ bta,
    float* __restrict__ out, __half* __restrict__ oh)
{
    __shared__ float sred[8];
    int row = blockIdx.x;
    int tid = threadIdx.x;
    const float* xr = x + (size_t)row * Dm;
    const float* yr = y + (size_t)row * Dm;

    float4 xv = *(const float4*)(xr + tid * 4);
    float4 yv = *(const float4*)(yr + tid * 4);
    float v[4] = {xv.x + yv.x, xv.y + yv.y, xv.z + yv.z, xv.w + yv.w};

    float sum = v[0] + v[1] + v[2] + v[3];
    sum = block_allreduce(sum, sred);
    float mean = sum * (1.f / (float)Dm);

    float sq = 0.f;
#pragma unroll
    for (int i = 0; i < 4; i++) {
        float d = v[i] - mean;
        sq += d * d;
    }
    sq = block_allreduce(sq, sred);
    float inv = rsqrtf(sq * (1.f / (float)Dm) + 1e-5f);

    float4 gv = *(const float4*)(g + tid * 4);
    float4 bv = *(const float4*)(bta + tid * 4);
    float o[4];
    o[0] = (v[0] - mean) * inv * gv.x + bv.x;
    o[1] = (v[1] - mean) * inv * gv.y + bv.y;
    o[2] = (v[2] - mean) * inv * gv.z + bv.z;
    o[3] = (v[3] - mean) * inv * gv.w + bv.w;
    *(float4*)(out + (size_t)row * Dm + tid * 4) =
        make_float4(o[0], o[1], o[2], o[3]);

    if (oh) {
        uint2 hv;
        hv.x = pack_f16x2(o[0], o[1]);
        hv.y = pack_f16x2(o[2], o[3]);
        *(uint2*)(oh + (size_t)row * Dm + tid * 4) = hv;
    }
}

// ===========================================================================
extern "C" void kernel_launch(void* const* d_in, const int* in_sizes, int n_in,
                              void* d_out, int out_size)
{
    const float* x     = (const float*)d_in[0];
    const float* in_w  = (const float*)d_in[1];
    const float* in_b  = (const float*)d_in[2];
    const float* out_w = (const float*)d_in[3];
    const float* out_b = (const float*)d_in[4];
    const float* w1    = (const float*)d_in[5];
    const float* b1    = (const float*)d_in[6];
    const float* w2    = (const float*)d_in[7];
    const float* b2    = (const float*)d_in[8];
    const float* ln1g  = (const float*)d_in[9];
    const float* ln1b  = (const float*)d_in[10];
    const float* ln2g  = (const float*)d_in[11];
    const float* ln2b  = (const float*)d_in[12];
    float* out = (float*)d_out;

    float *tmp, *hbuf;
    __half *xf, *wb, *qq, *kk, *vv, *at, *hf, *ff;
    cudaGetSymbolAddress((void**)&tmp, g_tmp);
    cudaGetSymbolAddress((void**)&hbuf, g_h);
    cudaGetSymbolAddress((void**)&xf, g_xf);
    cudaGetSymbolAddress((void**)&wb, g_wb);
    cudaGetSymbolAddress((void**)&qq, g_qq);
    cudaGetSymbolAddress((void**)&kk, g_kk);
    cudaGetSymbolAddress((void**)&vv, g_vv);
    cudaGetSymbolAddress((void**)&at, g_at);
    cudaGetSymbolAddress((void**)&hf, g_hf);
    cudaGetSymbolAddress((void**)&ff, g_ff);

    cudaFuncSetAttribute(gemm_f16, cudaFuncAttributeMaxDynamicSharedMemorySize,
                         3 * GSTG);
    cudaFuncSetAttribute(attn_mma, cudaFuncAttributeMaxDynamicSharedMemorySize,
                         ATT_SMEM);

    dim3 tb(256);

    rope_table_kernel<<<(Sq * 32 + 255) / 256, tb>>>();
    cvt_all<<<(SEG_W2 / 4 + 255) / 256, tb>>>(x, in_w, out_w, w1, w2);

    // QKV projection + fused RoPE -> head-major fp16 Q/K/V
    gemm_f16<<<dim3(3072 / 128, Mrows / 128), tb, 3 * GSTG>>>(
        xf, wb + OFF_INW, in_b, nullptr, nullptr, qq, kk, vv, 3 * Dm, Dm, 2);
    // Attention -> fp16
    attn_mma<<<dim3(Sq / 128, Bq * Hh), tb, ATT_SMEM>>>(qq, kk, vv, at);
    // Output projection -> fp32
    gemm_f16<<<dim3(Dm / 128, Mrows / 128), tb, 3 * GSTG>>>(
        at, wb + OFF_OUTW, out_b, tmp, nullptr, nullptr, nullptr, nullptr,
        Dm, Dm, 0);
    // LN1 -> fp32 h + fp16
    add_ln_kernel<<<Mrows, tb>>>(x, tmp, ln1g, ln1b, hbuf, hf);
    // FF1 + ReLU -> fp16
    gemm_f16<<<dim3(Ff / 128, Mrows / 128), tb, 3 * GSTG>>>(
        hf, wb + OFF_W1, b1, nullptr, ff, nullptr, nullptr, nullptr,
        Ff, Dm, 1);
    // FF2 -> fp32
    gemm_f16<<<dim3(Dm / 128, Mrows / 128), tb, 3 * GSTG>>>(
        ff, wb + OFF_W2, b2, tmp, nullptr, nullptr, nullptr, nullptr,
        Dm, Ff, 0);
    // LN2 -> out
    add_ln_kernel<<<Mrows, tb>>>(hbuf, tmp, ln2g, ln2b, out, nullptr);
}